// round 16
// baseline (speedup 1.0000x reference)
#include <cuda_runtime.h>
#include <cuda_fp16.h>
#include <stdint.h>

// CARAFE3d: B=1, C=64, D=H=W=32, c_mid=64, s=2, k=3, out_ch=32
#define N3 32768      // 32^3 coarse voxels
#define NF 262144     // 64^3 fine voxels

typedef unsigned long long u64;

// ---------------- global scratch ----------------
__device__ __align__(16) __half g_xf[N3 * 64];         // compressed feats fp16, [v][c]
__device__ __align__(16) __half g_wf[27 * 224 * 64];   // weights fp16 [t][o pad224][c], pre-swizzled
__device__ float g_w2[N3 * 216];                       // encode output, voxel-major [v][ch]
__device__ u64   g_p2[16 * N3];                        // projected x, oc-pairs

// ---------------- helpers ----------------
__device__ __forceinline__ u64 pk2(float lo, float hi) {
    u64 r; asm("mov.b64 %0, {%1, %2};" : "=l"(r) : "f"(lo), "f"(hi)); return r;
}
__device__ __forceinline__ void upk2(u64 v, float& lo, float& hi) {
    asm("mov.b64 {%0, %1}, %2;" : "=f"(lo), "=f"(hi) : "l"(v));
}
__device__ __forceinline__ u64 ffma2(u64 a, u64 b, u64 c) {
    u64 d; asm("fma.rn.f32x2 %0, %1, %2, %3;" : "=l"(d) : "l"(a), "l"(b), "l"(c));
    return d;
}
__device__ __forceinline__ unsigned hfpk(float lo, float hi) {  // mem order: lo first
    unsigned r; asm("cvt.rn.f16x2.f32 %0, %1, %2;" : "=r"(r) : "f"(hi), "f"(lo));
    return r;
}
__device__ __forceinline__ void cp16(uint32_t dst, const void* src) {
    asm volatile("cp.async.ca.shared.global [%0], [%1], 16;" :: "r"(dst), "l"(src));
}
// zero-fill variant: src-size 0 -> writes 16B of zeros, reads nothing
__device__ __forceinline__ void cp16z(uint32_t dst, const void* src, int srcsz) {
    asm volatile("cp.async.ca.shared.global [%0], [%1], 16, %2;"
                 :: "r"(dst), "l"(src), "r"(srcsz));
}
__device__ __forceinline__ void ldsm4(uint32_t* r, uint32_t addr) {
    asm volatile("ldmatrix.sync.aligned.m8n8.x4.shared.b16 {%0,%1,%2,%3}, [%4];"
                 : "=r"(r[0]), "=r"(r[1]), "=r"(r[2]), "=r"(r[3]) : "r"(addr));
}
__device__ __forceinline__ void ldsm2(uint32_t* r, uint32_t addr) {
    asm volatile("ldmatrix.sync.aligned.m8n8.x2.shared.b16 {%0,%1}, [%2];"
                 : "=r"(r[0]), "=r"(r[1]) : "r"(addr));
}
__device__ __forceinline__ void mma16816(float* c, const uint32_t* a, const uint32_t* b) {
    asm volatile("mma.sync.aligned.m16n8k16.row.col.f32.f16.f16.f32 "
                 "{%0,%1,%2,%3}, {%4,%5,%6,%7}, {%8,%9}, {%0,%1,%2,%3};"
                 : "+f"(c[0]), "+f"(c[1]), "+f"(c[2]), "+f"(c[3])
                 : "r"(a[0]), "r"(a[1]), "r"(a[2]), "r"(a[3]), "r"(b[0]), "r"(b[1]));
}

// ---------------------------------------------------------------------------
// Kernel 1a: 1x1x1 compress only -> fp16 voxel-major.  2 threads/voxel.
// ---------------------------------------------------------------------------
__global__ __launch_bounds__(256) void k_compress(const float* __restrict__ x,
                                                  const float* __restrict__ Wc,
                                                  const float* __restrict__ bc) {
    __shared__ __align__(16) u64 WB[64 * 36];
    __shared__ float bs[64];
    int tid = threadIdx.x;
    for (int i = tid; i < 2048; i += 256) {       // c(64) x p(32 pairs total)
        int c = i >> 5, j = i & 31;
        int sub = j >> 4, p = j & 15;
        int cm = sub * 32 + 2 * p;
        WB[c * 36 + sub * 18 + p] = pk2(Wc[cm * 64 + c], Wc[(cm + 1) * 64 + c]);
    }
    if (tid < 64) bs[tid] = bc[tid];
    __syncthreads();

    int v = blockIdx.x * 128 + (tid >> 1);
    int sub = tid & 1;
    u64 acc[16];
#pragma unroll
    for (int p = 0; p < 16; ++p) {
        int cm = sub * 32 + 2 * p;
        acc[p] = pk2(bs[cm], bs[cm + 1]);
    }

    const ulonglong2* wrow = (const ulonglong2*)&WB[sub * 18];
#pragma unroll 4
    for (int c = 0; c < 64; ++c) {
        float xv = x[c * N3 + v];
        u64 xd = pk2(xv, xv);
        const ulonglong2* row = wrow + c * 18;    // 18 ull2 per row (36 u64)
#pragma unroll
        for (int q = 0; q < 8; ++q) {
            ulonglong2 t = row[q];
            acc[2 * q]     = ffma2(xd, t.x, acc[2 * q]);
            acc[2 * q + 1] = ffma2(xd, t.y, acc[2 * q + 1]);
        }
    }

    float vals[32];
#pragma unroll
    for (int p = 0; p < 16; ++p) upk2(acc[p], vals[2 * p], vals[2 * p + 1]);
    uint4* xf4 = (uint4*)g_xf;
#pragma unroll
    for (int i = 0; i < 4; ++i) {
        unsigned hw[4];
#pragma unroll
        for (int j = 0; j < 4; ++j)
            hw[j] = hfpk(vals[i * 8 + 2 * j], vals[i * 8 + 2 * j + 1]);
        xf4[v * 8 + sub * 4 + i] = make_uint4(hw[0], hw[1], hw[2], hw[3]);
    }
}

// ---------------------------------------------------------------------------
// Kernel 1b: 1x1x1 projection of x (stream B, hidden under encode)
// ---------------------------------------------------------------------------
__global__ __launch_bounds__(256) void k_proj(const float* __restrict__ x,
                                              const float* __restrict__ Wp) {
    __shared__ __align__(16) float Ps[64 * 32];   // [c][oc]
    int tid = threadIdx.x;
    for (int i = tid; i < 2048; i += 256) {
        int c = i >> 5, oc = i & 31;
        Ps[i] = Wp[oc * 64 + c];
    }
    __syncthreads();
    int v = blockIdx.x * 256 + tid;
    const u64* ps64 = (const u64*)Ps;
    u64 acc[16];
#pragma unroll
    for (int p = 0; p < 16; ++p) acc[p] = 0ull;
#pragma unroll 2
    for (int c = 0; c < 64; ++c) {
        float xv = x[c * N3 + v];
        u64 xd = pk2(xv, xv);
#pragma unroll
        for (int p = 0; p < 16; ++p) acc[p] = ffma2(xd, ps64[c * 16 + p], acc[p]);
    }
#pragma unroll
    for (int p = 0; p < 16; ++p) g_p2[p * N3 + v] = acc[p];
}

// ---------------------------------------------------------------------------
// Kernel 1c: encode-weight prep (stream B, concurrent with compress)
// ---------------------------------------------------------------------------
__global__ __launch_bounds__(256) void k_wprep(const float* __restrict__ We) {
    int id = blockIdx.x * 256 + threadIdx.x;   // 27*216*64 = 373248
    int t = id / 13824;
    int r = id - t * 13824;
    int o = r >> 6, c = r & 63;
    float v = We[o * 1728 + c * 27 + t];
    int ci = c >> 3, j = c & 7;
    int dst = t * 14336 + o * 64 + ((ci ^ (o & 7)) << 3) + j;
    g_wf[dst] = __float2half(v);
}

// ---------------------------------------------------------------------------
// Kernel 2: encode conv, single-pass fp16 mma.sync GEMM.
// Persistent halo A-slab + producer warp (r15), now with 2-TAP SUPERSTEPS:
// 4-deep B ring, producer prefetches taps {2r+2,2r+3} while compute warps
// consume {2r,2r+1}.  Barriers 27 -> 14; producer always >=2 taps ahead.
// ---------------------------------------------------------------------------
#define HALO_ROWS 612                // 3*6*34
#define HALO_SZ   78336              // 612*128
#define B_TILE    28672              // 224 rows x 128 B

__global__ __launch_bounds__(288, 1) void k_encode_mma(const float* __restrict__ be) {
    extern __shared__ char dsraw[];
    char* dsm = (char*)(((uintptr_t)dsraw + 1023) & ~(uintptr_t)1023);
    uint32_t s_base = (uint32_t)__cvta_generic_to_shared(dsm);   // halo at +0
    __shared__ float bias[216];

    int tid = threadIdx.x;
    int wid = tid >> 5, lane = tid & 31;
    int b = blockIdx.x;
    int d = b >> 3, h0 = (b & 7) << 2;

    for (int i = tid; i < 216; i += 288) bias[i] = be[i];

    // ---- prologue: halo slab (zero-padded, swizzled) + B tiles for taps 0,1 ----
    {
        const uint4* xf4 = (const uint4*)g_xf;
        for (int i = tid; i < HALO_ROWS * 8; i += 288) {
            int s = i >> 3, ci = i & 7;
            int zd = s / 204; int rr = s - zd * 204;
            int zh = rr / 34; int zw = rr - zh * 34;
            int dd = d + zd - 1, hh = h0 + zh - 1, ww = zw - 1;
            bool ok = (unsigned)dd < 32u && (unsigned)hh < 32u && (unsigned)ww < 32u;
            int v = ok ? (dd * 1024 + hh * 32 + ww) * 8 + ci : 0;
            cp16z(s_base + s * 128 + ((ci ^ (s & 7)) << 4), xf4 + v, ok ? 16 : 0);
        }
        const char* srcB = (const char*)g_wf;
        for (int i = tid; i < 2 * 1792; i += 288)      // taps 0 and 1
            cp16(s_base + HALO_SZ + i * 16, srcB + i * 16);
        asm volatile("cp.async.commit_group;" ::: "memory");
        asm volatile("cp.async.wait_group 0;" ::: "memory");
        __syncthreads();
    }

    if (wid == 8) {
        // ---- producer warp: rounds of 2 taps; prefetch taps 2r+2, 2r+3 ----
        for (int r = 0; r < 14; ++r) {
#pragma unroll
            for (int q = 0; q < 2; ++q) {
                int tt = 2 * r + 2 + q;
                if (tt < 27) {
                    uint32_t bdst = s_base + HALO_SZ + (tt & 3) * B_TILE;
                    const char* srcB = (const char*)g_wf + tt * B_TILE;
                    for (int i = lane; i < 1792; i += 32)
                        cp16(bdst + i * 16, srcB + i * 16);
                }
            }
            asm volatile("cp.async.commit_group;" ::: "memory");
            asm volatile("cp.async.wait_group 0;" ::: "memory");
            __syncthreads();
        }
        return;   // no epilogue work
    }

    // ---------------- compute warps 0-7 ----------------
    int wm = wid & 1, wn = wid >> 1;     // m-warp (64 rows), n-group (7 subtiles)

    // per-lane constants
    int akh  = lane >> 4;                // A k-half
    int nr   = lane & 7;                 // B row within n8 subtile
    int bkh  = (lane >> 3) & 1;          // B k-half
    int tsel = lane >> 4;                // B subtile-within-pair
    uint32_t bpair0 = (uint32_t)(wn * 7 + tsel) * 1024 + nr * 128;
    uint32_t b6base = (uint32_t)(wn * 7 + 6) * 1024 + nr * 128;

    // per-mtile halo-row constants: srow = tapoff + cmt[mt]
    int cmt[4];
#pragma unroll
    for (int mt = 0; mt < 4; ++mt) {
        int m = wm * 64 + mt * 16 + (lane & 15);
        cmt[mt] = (m >> 5) * 34 + (m & 31);      // hr*34 + w
    }

    float acc[112];                      // [subtile j(7)][mtile(4)][4]
#pragma unroll
    for (int i = 0; i < 112; ++i) acc[i] = 0.f;

    for (int r = 0; r < 14; ++r) {
#pragma unroll
        for (int q = 0; q < 2; ++q) {
            int t = 2 * r + q;
            if (t >= 27) break;
            int kd = t / 9; int rr = t - kd * 9; int kh = rr / 3; int kw = rr - kh * 3;
            int tapoff = kd * 204 + kh * 34 + kw;

            uint32_t arow[4];
            int ax[4];
#pragma unroll
            for (int mt = 0; mt < 4; ++mt) {
                int srow = tapoff + cmt[mt];
                arow[mt] = s_base + srow * 128;
                ax[mt] = srow & 7;
            }
            uint32_t bstage = s_base + HALO_SZ + (t & 3) * B_TILE;

#pragma unroll
            for (int ks = 0; ks < 4; ++ks) {
                int kc = (ks << 1) | akh;
                uint32_t a[4][4];
#pragma unroll
                for (int mt = 0; mt < 4; ++mt)
                    ldsm4(a[mt], arow[mt] + ((kc ^ ax[mt]) << 4));

                uint32_t bswz = ((((ks << 1) | bkh)) ^ nr) << 4;
                uint32_t bp[3][4], b6[2];
#pragma unroll
                for (int jp = 0; jp < 3; ++jp)
                    ldsm4(bp[jp], bstage + bpair0 + jp * 2048 + bswz);
                ldsm2(b6, bstage + b6base + bswz);

#pragma unroll
                for (int jp = 0; jp < 3; ++jp) {
#pragma unroll
                    for (int mt = 0; mt < 4; ++mt) {
                        mma16816(&acc[(2 * jp) * 16 + mt * 4], a[mt], bp[jp]);
                        mma16816(&acc[(2 * jp + 1) * 16 + mt * 4], a[mt], bp[jp] + 2);
                    }
                }
#pragma unroll
                for (int mt = 0; mt < 4; ++mt)
                    mma16816(&acc[96 + mt * 4], a[mt], b6);
            }
        }
        __syncthreads();
    }

    // epilogue: c-frag -> g_w2 voxel-major [v][216] with bias, 8B v2 stores.
    int g = lane >> 2, tq = lane & 3;
    int vbase = d * 1024 + h0 * 32;
#pragma unroll
    for (int j = 0; j < 7; ++j) {
        if (wn == 3 && j == 6) break;     // subtile 27 is pad
        int c0 = (wn * 7 + j) * 8 + 2 * tq;
        float b0v = bias[c0], b1v = bias[c0 + 1];
#pragma unroll
        for (int mt = 0; mt < 4; ++mt) {
            int r = wm * 64 + mt * 16 + g;
            const float* cp = &acc[j * 16 + mt * 4];
            *(float2*)&g_w2[(u64)(vbase + r) * 216 + c0] =
                make_float2(cp[0] + b0v, cp[1] + b1v);
            *(float2*)&g_w2[(u64)(vbase + r + 8) * 216 + c0] =
                make_float2(cp[2] + b0v, cp[3] + b1v);
        }
    }
}

// ---------------------------------------------------------------------------
// Kernel 3: fused pixelshuffle + softmax(27) + factored reassembly.
// ---------------------------------------------------------------------------
#define OPAD 68
__global__ __launch_bounds__(256) void k_reassemble(float* __restrict__ out) {
    extern __shared__ char rsm[];
    u64*   ps   = (u64*)rsm;                      // 16*306 u64 (39168 B)
    float* obuf = (float*)rsm;                    // reused post-compute: 128*68*4 B

    int tid = threadIdx.x;
    int h = blockIdx.x, d = blockIdx.y;
    int off = tid & 7;                            // pd*4 + qh*2 + rw
    int w = tid >> 3;                             // 0..31
    int pd = off >> 2, qh = (off >> 1) & 1, rw = off & 1;
    int vbase = d * 1024 + h * 32;

    // projected-patch slab (replicate padding)
    for (int i = tid; i < 16 * 306; i += 256) {
        int pp = i / 306; int r = i - pp * 306;
        int kd = r / 102; int r2 = r - kd * 102;
        int kh = r2 / 34; int ii = r2 - kh * 34;
        int dd = min(max(d + kd - 1, 0), 31);
        int hh = min(max(h + kh - 1, 0), 31);
        int ww = min(max(ii - 1, 0), 31);
        ps[i] = g_p2[pp * N3 + dd * 1024 + hh * 32 + ww];
    }
    __syncthreads();

    // softmax over 27 taps: logits at g_w2[v][k*8 + off]
    const float* w2v = &g_w2[(u64)(vbase + w) * 216];
    float sw[27];
    float m = -1e30f;
#pragma unroll
    for (int k = 0; k < 27; ++k) {
        float v = w2v[k * 8 + off];
        sw[k] = v;
        m = fmaxf(m, v);
    }
    float s = 0.f;
#pragma unroll
    for (int k = 0; k < 27; ++k) { sw[k] = __expf(sw[k] - m); s += sw[k]; }
    float inv = 1.f / s;
#pragma unroll
    for (int k = 0; k < 27; ++k) sw[k] *= inv;

    u64 acc[16];
#pragma unroll
    for (int p = 0; p < 16; ++p) acc[p] = 0ull;
#pragma unroll
    for (int kd = 0; kd < 3; ++kd)
#pragma unroll
        for (int kh = 0; kh < 3; ++kh)
#pragma unroll
            for (int kw = 0; kw < 3; ++kw) {
                float sv = sw[(kd * 3 + kh) * 3 + kw];
                u64 sd = pk2(sv, sv);
                int base = kd * 102 + kh * 34 + w + kw;
#pragma unroll
                for (int p = 0; p < 16; ++p)
                    acc[p] = ffma2(sd, ps[p * 306 + base], acc[p]);
            }
    __syncthreads();   // everyone done reading ps; safe to overwrite with obuf

    // stage outputs: row = ch*4 + pd*2 + qh (128 rows), col = 2w+rw (64 cols)
    int rowbase = pd * 2 + qh;
    int col = 2 * w + rw;
#pragma unroll
    for (int p = 0; p < 16; ++p) {
        float a, bb; upk2(acc[p], a, bb);
        obuf[((2 * p) * 4 + rowbase) * OPAD + col]     = a;
        obuf[((2 * p + 1) * 4 + rowbase) * OPAD + col] = bb;
    }
    __syncthreads();

    // coalesced stores: 128 rows x 256B contiguous
    int d2b = 2 * d, h2b = 2 * h;
    for (int i = tid; i < 2048; i += 256) {      // i indexes float4
        int row = i >> 4, c4 = (i & 15) << 2;
        int ch = row >> 2, pdq = row & 3;
        float4 v = *(float4*)&obuf[row * OPAD + c4];
        *(float4*)&out[(u64)ch * NF + (d2b + (pdq >> 1)) * 4096 +
                       (h2b + (pdq & 1)) * 64 + c4] = v;
    }
}

// ---------------------------------------------------------------------------
extern "C" void kernel_launch(void* const* d_in, const int* in_sizes, int n_in,
                              void* d_out, int out_size) {
    const float* x  = (const float*)d_in[0];
    const float* wc = (const float*)d_in[1];
    const float* bc = (const float*)d_in[2];
    const float* we = (const float*)d_in[3];
    const float* be = (const float*)d_in[4];
    const float* wp = (const float*)d_in[5];
    float* out = (float*)d_out;

    const int enc_smem = HALO_SZ + 4 * B_TILE + 1024;   // 194048
    const int rea_smem = 16 * 306 * 8;                  // 39168

    static cudaStream_t sB = nullptr;
    static cudaEvent_t evF = nullptr, evW = nullptr, evP = nullptr;
    static int inited = 0;
    if (!inited) {
        cudaFuncSetAttribute(k_encode_mma, cudaFuncAttributeMaxDynamicSharedMemorySize,
                             enc_smem);
        cudaFuncSetAttribute(k_reassemble, cudaFuncAttributeMaxDynamicSharedMemorySize,
                             rea_smem);
        cudaStreamCreateWithFlags(&sB, cudaStreamNonBlocking);
        cudaEventCreateWithFlags(&evF, cudaEventDisableTiming);
        cudaEventCreateWithFlags(&evW, cudaEventDisableTiming);
        cudaEventCreateWithFlags(&evP, cudaEventDisableTiming);
        inited = 1;
    }

    // fork side stream from the (capturable) default stream
    cudaEventRecord(evF, 0);
    cudaStreamWaitEvent(sB, evF, 0);
    k_wprep<<<1458, 256, 0, sB>>>(we);        // needed by encode
    cudaEventRecord(evW, sB);
    k_proj<<<128, 256, 0, sB>>>(x, wp);       // needed by reassemble only
    cudaEventRecord(evP, sB);

    // main chain on default stream (concurrent with sB where legal)
    k_compress<<<256, 256>>>(x, wc, bc);
    cudaStreamWaitEvent(0, evW, 0);           // encode needs g_wf
    k_encode_mma<<<256, 288, enc_smem>>>(be);
    cudaStreamWaitEvent(0, evP, 0);           // reassemble needs g_p2
    k_reassemble<<<dim3(32, 32), 256, rea_smem>>>(out);
}

// round 17
// speedup vs baseline: 1.0290x; 1.0290x over previous
#include <cuda_runtime.h>
#include <cuda_fp16.h>
#include <stdint.h>

// CARAFE3d: B=1, C=64, D=H=W=32, c_mid=64, s=2, k=3, out_ch=32
#define N3 32768      // 32^3 coarse voxels
#define NF 262144     // 64^3 fine voxels

typedef unsigned long long u64;

// ---------------- global scratch ----------------
__device__ __align__(16) __half g_xf[N3 * 64];         // compressed feats fp16, [v][c]
__device__ __align__(16) __half g_wf[27 * 224 * 64];   // weights fp16 [t][o pad224][c], pre-swizzled
__device__ float g_w2[N3 * 216];                       // encode output, voxel-major [v][ch]
__device__ u64   g_p2[16 * N3];                        // projected x, oc-pairs

// ---------------- helpers ----------------
__device__ __forceinline__ u64 pk2(float lo, float hi) {
    u64 r; asm("mov.b64 %0, {%1, %2};" : "=l"(r) : "f"(lo), "f"(hi)); return r;
}
__device__ __forceinline__ void upk2(u64 v, float& lo, float& hi) {
    asm("mov.b64 {%0, %1}, %2;" : "=f"(lo), "=f"(hi) : "l"(v));
}
__device__ __forceinline__ u64 ffma2(u64 a, u64 b, u64 c) {
    u64 d; asm("fma.rn.f32x2 %0, %1, %2, %3;" : "=l"(d) : "l"(a), "l"(b), "l"(c));
    return d;
}
__device__ __forceinline__ unsigned hfpk(float lo, float hi) {  // mem order: lo first
    unsigned r; asm("cvt.rn.f16x2.f32 %0, %1, %2;" : "=r"(r) : "f"(hi), "f"(lo));
    return r;
}
__device__ __forceinline__ void cp16(uint32_t dst, const void* src) {
    asm volatile("cp.async.ca.shared.global [%0], [%1], 16;" :: "r"(dst), "l"(src));
}
// zero-fill variant: src-size 0 -> writes 16B of zeros, reads nothing
__device__ __forceinline__ void cp16z(uint32_t dst, const void* src, int srcsz) {
    asm volatile("cp.async.ca.shared.global [%0], [%1], 16, %2;"
                 :: "r"(dst), "l"(src), "r"(srcsz));
}
__device__ __forceinline__ void ldsm4(uint32_t* r, uint32_t addr) {
    asm volatile("ldmatrix.sync.aligned.m8n8.x4.shared.b16 {%0,%1,%2,%3}, [%4];"
                 : "=r"(r[0]), "=r"(r[1]), "=r"(r[2]), "=r"(r[3]) : "r"(addr));
}
__device__ __forceinline__ void ldsm2(uint32_t* r, uint32_t addr) {
    asm volatile("ldmatrix.sync.aligned.m8n8.x2.shared.b16 {%0,%1}, [%2];"
                 : "=r"(r[0]), "=r"(r[1]) : "r"(addr));
}
__device__ __forceinline__ void mma16816(float* c, const uint32_t* a, const uint32_t* b) {
    asm volatile("mma.sync.aligned.m16n8k16.row.col.f32.f16.f16.f32 "
                 "{%0,%1,%2,%3}, {%4,%5,%6,%7}, {%8,%9}, {%0,%1,%2,%3};"
                 : "+f"(c[0]), "+f"(c[1]), "+f"(c[2]), "+f"(c[3])
                 : "r"(a[0]), "r"(a[1]), "r"(a[2]), "r"(a[3]), "r"(b[0]), "r"(b[1]));
}

// ---------------------------------------------------------------------------
// Kernel 1a: 1x1x1 compress only -> fp16 voxel-major.  2 threads/voxel.
// ---------------------------------------------------------------------------
__global__ __launch_bounds__(256) void k_compress(const float* __restrict__ x,
                                                  const float* __restrict__ Wc,
                                                  const float* __restrict__ bc) {
    __shared__ __align__(16) u64 WB[64 * 36];
    __shared__ float bs[64];
    int tid = threadIdx.x;
    for (int i = tid; i < 2048; i += 256) {       // c(64) x p(32 pairs total)
        int c = i >> 5, j = i & 31;
        int sub = j >> 4, p = j & 15;
        int cm = sub * 32 + 2 * p;
        WB[c * 36 + sub * 18 + p] = pk2(Wc[cm * 64 + c], Wc[(cm + 1) * 64 + c]);
    }
    if (tid < 64) bs[tid] = bc[tid];
    __syncthreads();

    int v = blockIdx.x * 128 + (tid >> 1);
    int sub = tid & 1;
    u64 acc[16];
#pragma unroll
    for (int p = 0; p < 16; ++p) {
        int cm = sub * 32 + 2 * p;
        acc[p] = pk2(bs[cm], bs[cm + 1]);
    }

    const ulonglong2* wrow = (const ulonglong2*)&WB[sub * 18];
#pragma unroll 4
    for (int c = 0; c < 64; ++c) {
        float xv = x[c * N3 + v];
        u64 xd = pk2(xv, xv);
        const ulonglong2* row = wrow + c * 18;    // 18 ull2 per row (36 u64)
#pragma unroll
        for (int q = 0; q < 8; ++q) {
            ulonglong2 t = row[q];
            acc[2 * q]     = ffma2(xd, t.x, acc[2 * q]);
            acc[2 * q + 1] = ffma2(xd, t.y, acc[2 * q + 1]);
        }
    }

    float vals[32];
#pragma unroll
    for (int p = 0; p < 16; ++p) upk2(acc[p], vals[2 * p], vals[2 * p + 1]);
    uint4* xf4 = (uint4*)g_xf;
#pragma unroll
    for (int i = 0; i < 4; ++i) {
        unsigned hw[4];
#pragma unroll
        for (int j = 0; j < 4; ++j)
            hw[j] = hfpk(vals[i * 8 + 2 * j], vals[i * 8 + 2 * j + 1]);
        xf4[v * 8 + sub * 4 + i] = make_uint4(hw[0], hw[1], hw[2], hw[3]);
    }
}

// ---------------------------------------------------------------------------
// Kernel 1b: 1x1x1 projection of x (stream B, hidden under encode)
// ---------------------------------------------------------------------------
__global__ __launch_bounds__(256) void k_proj(const float* __restrict__ x,
                                              const float* __restrict__ Wp) {
    __shared__ __align__(16) float Ps[64 * 32];   // [c][oc]
    int tid = threadIdx.x;
    for (int i = tid; i < 2048; i += 256) {
        int c = i >> 5, oc = i & 31;
        Ps[i] = Wp[oc * 64 + c];
    }
    __syncthreads();
    int v = blockIdx.x * 256 + tid;
    const u64* ps64 = (const u64*)Ps;
    u64 acc[16];
#pragma unroll
    for (int p = 0; p < 16; ++p) acc[p] = 0ull;
#pragma unroll 2
    for (int c = 0; c < 64; ++c) {
        float xv = x[c * N3 + v];
        u64 xd = pk2(xv, xv);
#pragma unroll
        for (int p = 0; p < 16; ++p) acc[p] = ffma2(xd, ps64[c * 16 + p], acc[p]);
    }
#pragma unroll
    for (int p = 0; p < 16; ++p) g_p2[p * N3 + v] = acc[p];
}

// ---------------------------------------------------------------------------
// Kernel 1c: encode-weight prep (stream B, concurrent with compress)
// ---------------------------------------------------------------------------
__global__ __launch_bounds__(256) void k_wprep(const float* __restrict__ We) {
    int id = blockIdx.x * 256 + threadIdx.x;   // 27*216*64 = 373248
    int t = id / 13824;
    int r = id - t * 13824;
    int o = r >> 6, c = r & 63;
    float v = We[o * 1728 + c * 27 + t];
    int ci = c >> 3, j = c & 7;
    int dst = t * 14336 + o * 64 + ((ci ^ (o & 7)) << 3) + j;
    g_wf[dst] = __float2half(v);
}

// ---------------------------------------------------------------------------
// Kernel 2: encode conv, single-pass fp16 mma.sync GEMM (r16 best config:
// persistent halo A-slab, producer warp, 2-tap supersteps / 4-deep B ring).
// ---------------------------------------------------------------------------
#define HALO_ROWS 612                // 3*6*34
#define HALO_SZ   78336              // 612*128
#define B_TILE    28672              // 224 rows x 128 B

__global__ __launch_bounds__(288, 1) void k_encode_mma(const float* __restrict__ be) {
    extern __shared__ char dsraw[];
    char* dsm = (char*)(((uintptr_t)dsraw + 1023) & ~(uintptr_t)1023);
    uint32_t s_base = (uint32_t)__cvta_generic_to_shared(dsm);   // halo at +0
    __shared__ float bias[216];

    int tid = threadIdx.x;
    int wid = tid >> 5, lane = tid & 31;
    int b = blockIdx.x;
    int d = b >> 3, h0 = (b & 7) << 2;

    for (int i = tid; i < 216; i += 288) bias[i] = be[i];

    // ---- prologue: halo slab (zero-padded, swizzled) + B tiles for taps 0,1 ----
    {
        const uint4* xf4 = (const uint4*)g_xf;
        for (int i = tid; i < HALO_ROWS * 8; i += 288) {
            int s = i >> 3, ci = i & 7;
            int zd = s / 204; int rr = s - zd * 204;
            int zh = rr / 34; int zw = rr - zh * 34;
            int dd = d + zd - 1, hh = h0 + zh - 1, ww = zw - 1;
            bool ok = (unsigned)dd < 32u && (unsigned)hh < 32u && (unsigned)ww < 32u;
            int v = ok ? (dd * 1024 + hh * 32 + ww) * 8 + ci : 0;
            cp16z(s_base + s * 128 + ((ci ^ (s & 7)) << 4), xf4 + v, ok ? 16 : 0);
        }
        const char* srcB = (const char*)g_wf;
        for (int i = tid; i < 2 * 1792; i += 288)      // taps 0 and 1
            cp16(s_base + HALO_SZ + i * 16, srcB + i * 16);
        asm volatile("cp.async.commit_group;" ::: "memory");
        asm volatile("cp.async.wait_group 0;" ::: "memory");
        __syncthreads();
    }

    if (wid == 8) {
        // ---- producer warp: rounds of 2 taps; prefetch taps 2r+2, 2r+3 ----
        for (int r = 0; r < 14; ++r) {
#pragma unroll
            for (int q = 0; q < 2; ++q) {
                int tt = 2 * r + 2 + q;
                if (tt < 27) {
                    uint32_t bdst = s_base + HALO_SZ + (tt & 3) * B_TILE;
                    const char* srcB = (const char*)g_wf + tt * B_TILE;
                    for (int i = lane; i < 1792; i += 32)
                        cp16(bdst + i * 16, srcB + i * 16);
                }
            }
            asm volatile("cp.async.commit_group;" ::: "memory");
            asm volatile("cp.async.wait_group 0;" ::: "memory");
            __syncthreads();
        }
        return;   // no epilogue work
    }

    // ---------------- compute warps 0-7 ----------------
    int wm = wid & 1, wn = wid >> 1;     // m-warp (64 rows), n-group (7 subtiles)

    // per-lane constants
    int akh  = lane >> 4;                // A k-half
    int nr   = lane & 7;                 // B row within n8 subtile
    int bkh  = (lane >> 3) & 1;          // B k-half
    int tsel = lane >> 4;                // B subtile-within-pair
    uint32_t bpair0 = (uint32_t)(wn * 7 + tsel) * 1024 + nr * 128;
    uint32_t b6base = (uint32_t)(wn * 7 + 6) * 1024 + nr * 128;

    // per-mtile halo-row constants: srow = tapoff + cmt[mt]
    int cmt[4];
#pragma unroll
    for (int mt = 0; mt < 4; ++mt) {
        int m = wm * 64 + mt * 16 + (lane & 15);
        cmt[mt] = (m >> 5) * 34 + (m & 31);      // hr*34 + w
    }

    float acc[112];                      // [subtile j(7)][mtile(4)][4]
#pragma unroll
    for (int i = 0; i < 112; ++i) acc[i] = 0.f;

    for (int r = 0; r < 14; ++r) {
#pragma unroll
        for (int q = 0; q < 2; ++q) {
            int t = 2 * r + q;
            if (t >= 27) break;
            int kd = t / 9; int rr = t - kd * 9; int kh = rr / 3; int kw = rr - kh * 3;
            int tapoff = kd * 204 + kh * 34 + kw;

            uint32_t arow[4];
            int ax[4];
#pragma unroll
            for (int mt = 0; mt < 4; ++mt) {
                int srow = tapoff + cmt[mt];
                arow[mt] = s_base + srow * 128;
                ax[mt] = srow & 7;
            }
            uint32_t bstage = s_base + HALO_SZ + (t & 3) * B_TILE;

#pragma unroll
            for (int ks = 0; ks < 4; ++ks) {
                int kc = (ks << 1) | akh;
                uint32_t a[4][4];
#pragma unroll
                for (int mt = 0; mt < 4; ++mt)
                    ldsm4(a[mt], arow[mt] + ((kc ^ ax[mt]) << 4));

                uint32_t bswz = ((((ks << 1) | bkh)) ^ nr) << 4;
                uint32_t bp[3][4], b6[2];
#pragma unroll
                for (int jp = 0; jp < 3; ++jp)
                    ldsm4(bp[jp], bstage + bpair0 + jp * 2048 + bswz);
                ldsm2(b6, bstage + b6base + bswz);

#pragma unroll
                for (int jp = 0; jp < 3; ++jp) {
#pragma unroll
                    for (int mt = 0; mt < 4; ++mt) {
                        mma16816(&acc[(2 * jp) * 16 + mt * 4], a[mt], bp[jp]);
                        mma16816(&acc[(2 * jp + 1) * 16 + mt * 4], a[mt], bp[jp] + 2);
                    }
                }
#pragma unroll
                for (int mt = 0; mt < 4; ++mt)
                    mma16816(&acc[96 + mt * 4], a[mt], b6);
            }
        }
        __syncthreads();
    }

    // epilogue: c-frag -> g_w2 voxel-major [v][216] with bias, 8B v2 stores.
    int g = lane >> 2, tq = lane & 3;
    int vbase = d * 1024 + h0 * 32;
#pragma unroll
    for (int j = 0; j < 7; ++j) {
        if (wn == 3 && j == 6) break;     // subtile 27 is pad
        int c0 = (wn * 7 + j) * 8 + 2 * tq;
        float b0v = bias[c0], b1v = bias[c0 + 1];
#pragma unroll
        for (int mt = 0; mt < 4; ++mt) {
            int r = wm * 64 + mt * 16 + g;
            const float* cp = &acc[j * 16 + mt * 4];
            *(float2*)&g_w2[(u64)(vbase + r) * 216 + c0] =
                make_float2(cp[0] + b0v, cp[1] + b1v);
            *(float2*)&g_w2[(u64)(vbase + r + 8) * 216 + c0] =
                make_float2(cp[2] + b0v, cp[3] + b1v);
        }
    }
}

// ---------------------------------------------------------------------------
// Kernel 3: fused pixelshuffle + softmax(27) + factored reassembly.
// 512 THREADS: thread sub-half (tid>>8) owns 8 of the 16 oc-pairs -> half the
// acc regs, 2x warps for the L2-latency-bound slab gather.  Softmax repeated
// per sub-half (27 broadcast L2 reads, cheaper than an extra smem pass+sync).
// ---------------------------------------------------------------------------
#define OPAD 68
__global__ __launch_bounds__(512) void k_reassemble(float* __restrict__ out) {
    extern __shared__ char rsm[];
    u64*   ps   = (u64*)rsm;                      // 16*306 u64 (39168 B)
    float* obuf = (float*)rsm;                    // reused post-compute: 128*68*4 B

    int tid = threadIdx.x;
    int h = blockIdx.x, d = blockIdx.y;
    int off = tid & 7;                            // pd*4 + qh*2 + rw
    int w = (tid >> 3) & 31;                      // 0..31
    int sub = tid >> 8;                           // oc-half this thread owns
    int pd = off >> 2, qh = (off >> 1) & 1, rw = off & 1;
    int vbase = d * 1024 + h * 32;

    // projected-patch slab (replicate padding)
    for (int i = tid; i < 16 * 306; i += 512) {
        int pp = i / 306; int r = i - pp * 306;
        int kd = r / 102; int r2 = r - kd * 102;
        int kh = r2 / 34; int ii = r2 - kh * 34;
        int dd = min(max(d + kd - 1, 0), 31);
        int hh = min(max(h + kh - 1, 0), 31);
        int ww = min(max(ii - 1, 0), 31);
        ps[i] = g_p2[pp * N3 + dd * 1024 + hh * 32 + ww];
    }
    __syncthreads();

    // softmax over 27 taps: logits at g_w2[v][k*8 + off]
    const float* w2v = &g_w2[(u64)(vbase + w) * 216];
    float sw[27];
    float m = -1e30f;
#pragma unroll
    for (int k = 0; k < 27; ++k) {
        float v = w2v[k * 8 + off];
        sw[k] = v;
        m = fmaxf(m, v);
    }
    float s = 0.f;
#pragma unroll
    for (int k = 0; k < 27; ++k) { sw[k] = __expf(sw[k] - m); s += sw[k]; }
    float inv = 1.f / s;
#pragma unroll
    for (int k = 0; k < 27; ++k) sw[k] *= inv;

    u64 acc[8];
#pragma unroll
    for (int q = 0; q < 8; ++q) acc[q] = 0ull;
    const u64* psub = ps + (sub * 8) * 306;
#pragma unroll
    for (int kd = 0; kd < 3; ++kd)
#pragma unroll
        for (int kh = 0; kh < 3; ++kh)
#pragma unroll
            for (int kw = 0; kw < 3; ++kw) {
                float sv = sw[(kd * 3 + kh) * 3 + kw];
                u64 sd = pk2(sv, sv);
                int base = kd * 102 + kh * 34 + w + kw;
#pragma unroll
                for (int q = 0; q < 8; ++q)
                    acc[q] = ffma2(sd, psub[q * 306 + base], acc[q]);
            }
    __syncthreads();   // everyone done reading ps; safe to overwrite with obuf

    // stage outputs: row = ch*4 + pd*2 + qh (128 rows), col = 2w+rw (64 cols)
    int rowbase = pd * 2 + qh;
    int col = 2 * w + rw;
#pragma unroll
    for (int q = 0; q < 8; ++q) {
        int p = sub * 8 + q;
        float a, bb; upk2(acc[q], a, bb);
        obuf[((2 * p) * 4 + rowbase) * OPAD + col]     = a;
        obuf[((2 * p + 1) * 4 + rowbase) * OPAD + col] = bb;
    }
    __syncthreads();

    // coalesced stores: 128 rows x 256B contiguous
    int d2b = 2 * d, h2b = 2 * h;
    for (int i = tid; i < 2048; i += 512) {      // i indexes float4
        int row = i >> 4, c4 = (i & 15) << 2;
        int ch = row >> 2, pdq = row & 3;
        float4 v = *(float4*)&obuf[row * OPAD + c4];
        *(float4*)&out[(u64)ch * NF + (d2b + (pdq >> 1)) * 4096 +
                       (h2b + (pdq & 1)) * 64 + c4] = v;
    }
}

// ---------------------------------------------------------------------------
extern "C" void kernel_launch(void* const* d_in, const int* in_sizes, int n_in,
                              void* d_out, int out_size) {
    const float* x  = (const float*)d_in[0];
    const float* wc = (const float*)d_in[1];
    const float* bc = (const float*)d_in[2];
    const float* we = (const float*)d_in[3];
    const float* be = (const float*)d_in[4];
    const float* wp = (const float*)d_in[5];
    float* out = (float*)d_out;

    const int enc_smem = HALO_SZ + 4 * B_TILE + 1024;   // 194048
    const int rea_smem = 16 * 306 * 8;                  // 39168

    static cudaStream_t sB = nullptr;
    static cudaEvent_t evF = nullptr, evW = nullptr, evP = nullptr;
    static int inited = 0;
    if (!inited) {
        cudaFuncSetAttribute(k_encode_mma, cudaFuncAttributeMaxDynamicSharedMemorySize,
                             enc_smem);
        cudaFuncSetAttribute(k_reassemble, cudaFuncAttributeMaxDynamicSharedMemorySize,
                             rea_smem);
        cudaStreamCreateWithFlags(&sB, cudaStreamNonBlocking);
        cudaEventCreateWithFlags(&evF, cudaEventDisableTiming);
        cudaEventCreateWithFlags(&evW, cudaEventDisableTiming);
        cudaEventCreateWithFlags(&evP, cudaEventDisableTiming);
        inited = 1;
    }

    // fork side stream from the (capturable) default stream
    cudaEventRecord(evF, 0);
    cudaStreamWaitEvent(sB, evF, 0);
    k_wprep<<<1458, 256, 0, sB>>>(we);        // needed by encode
    cudaEventRecord(evW, sB);
    k_proj<<<128, 256, 0, sB>>>(x, wp);       // needed by reassemble only
    cudaEventRecord(evP, sB);

    // main chain on default stream (concurrent with sB where legal)
    k_compress<<<256, 256>>>(x, wc, bc);
    cudaStreamWaitEvent(0, evW, 0);           // encode needs g_wf
    k_encode_mma<<<256, 288, enc_smem>>>(be);
    cudaStreamWaitEvent(0, evP, 0);           // reassemble needs g_p2
    k_reassemble<<<dim3(32, 32), 512, rea_smem>>>(out);
}